// round 3
// baseline (speedup 1.0000x reference)
#include <cuda_runtime.h>

#define TPB       512
#define TOK_CTA   256
#define TOK_TILE  64
#define NTILES    (TOK_CTA / TOK_TILE)   // 4
#define MT        (TOK_TILE / 16)        // 4 m-tiles per tile
#define NE        8
#define NH        64
#define DIM       64
#define GHD       32

__device__ __forceinline__ unsigned f2tf(float f) {
    unsigned u;
    asm("cvt.rna.tf32.f32 %0, %1;" : "=r"(u) : "f"(f));
    return u;
}
__device__ __forceinline__ void mma_tf32(float* c,
                                         unsigned a0, unsigned a1, unsigned a2, unsigned a3,
                                         unsigned b0, unsigned b1) {
    asm volatile(
        "mma.sync.aligned.m16n8k8.row.col.f32.tf32.tf32.f32 "
        "{%0,%1,%2,%3}, {%4,%5,%6,%7}, {%8,%9}, {%0,%1,%2,%3};\n"
        : "+f"(c[0]), "+f"(c[1]), "+f"(c[2]), "+f"(c[3])
        : "r"(a0), "r"(a1), "r"(a2), "r"(a3), "r"(b0), "r"(b1));
}

__global__ void __launch_bounds__(TPB, 2)
moe_mma_kernel(const float* __restrict__ A,  const float* __restrict__ S,
               const float* __restrict__ gw1, const float* __restrict__ gb1,
               const float* __restrict__ gw2, const float* __restrict__ gb2,
               const float* __restrict__ ew1, const float* __restrict__ eb1,
               const float* __restrict__ ew2, const float* __restrict__ eb2,
               float* __restrict__ out)
{
    __shared__ uint4    XSv[MT * 8 * 32];     // A-frags, 16KB
    __shared__ unsigned GHu[TOK_TILE * 33];   // gating hidden (tf32 bits)
    __shared__ float    EO[TOK_TILE * 18];    // [token][expert*2+half]
    __shared__ float    Psm[TOK_TILE * 9];    // gating probs
    __shared__ float    sw2[NE * NH];
    __shared__ float    sb1[NE * NH];
    __shared__ float    sb2[NE];

    const int tid  = threadIdx.x;
    const int w    = tid >> 5;                // 0..15
    const int lane = tid & 31;
    const int g    = lane >> 2;
    const int tig  = lane & 3;
    const int e    = w >> 1;                  // expert id
    const int nh   = w & 1;                   // n-half (nt base = nh*4)

    for (int i = tid; i < NE * NH; i += TPB) { sw2[i] = ew2[i]; sb1[i] = eb1[i]; }
    if (tid < NE) sb2[tid] = eb2[tid];

    // expert B-fragments: 4 n-tiles x 8 k-tiles = 64 regs
    unsigned bf[4][8][2];
    {
        const float* we = ew1 + e * (DIM * NH);
        #pragma unroll
        for (int nt = 0; nt < 4; nt++)
            #pragma unroll
            for (int kt = 0; kt < 8; kt++) {
                const int ncol = (nh*4 + nt)*8 + g;
                bf[nt][kt][0] = f2tf(we[(kt*8 + tig    ) * NH + ncol]);
                bf[nt][kt][1] = f2tf(we[(kt*8 + tig + 4) * NH + ncol]);
            }
    }

    // gating fragments (warps 0-3: layer1 n-tile w; warp 4: layer2) — shared regs
    unsigned gf0[4], gf1[4]; float gba = 0.f, gbb = 0.f;
    if (w < 4) {
        #pragma unroll
        for (int kt = 0; kt < 4; kt++) {
            gf0[kt] = f2tf(gw1[(kt*8 + tig    ) * GHD + w*8 + g]);
            gf1[kt] = f2tf(gw1[(kt*8 + tig + 4) * GHD + w*8 + g]);
        }
        gba = gb1[w*8 + 2*tig];
        gbb = gb1[w*8 + 2*tig + 1];
    } else if (w == 4) {
        #pragma unroll
        for (int kt = 0; kt < 4; kt++) {
            gf0[kt] = f2tf(gw2[(kt*8 + tig    ) * NE + g]);
            gf1[kt] = f2tf(gw2[(kt*8 + tig + 4) * NE + g]);
        }
        gba = gb2[2*tig];
        gbb = gb2[2*tig + 1];
    }

    const int ctaBase = blockIdx.x * TOK_CTA;
    unsigned* XS = (unsigned*)XSv;

    #pragma unroll 1
    for (int it = 0; it < NTILES; it++) {
        const int tb = ctaBase + it * TOK_TILE;

        __syncthreads();   // bar1: prev EO/Psm consumed below; XS free

        if (it > 0 && tid < TOK_TILE) {
            float a = 0.f;
            #pragma unroll
            for (int ee = 0; ee < NE; ee++)
                a = fmaf(Psm[tid*9 + ee], EO[tid*18 + 2*ee] + EO[tid*18 + 2*ee + 1], a);
            out[tb - TOK_TILE + tid] = a;
        }

        // stage 64 tokens into A-fragment-ordered smem
        #pragma unroll
        for (int j = tid; j < TOK_TILE * 16; j += TPB) {
            const int t  = j >> 4;
            const int dq = j & 15;
            float4 v;
            if (dq < 8) v = ((const float4*)A)[(size_t)(tb + t) * 8 + dq];
            else        v = ((const float4*)S)[(size_t)(tb + t) * 8 + (dq - 8)];
            const int mt = t >> 4, ri = t & 15;
            const int gg = ri & 7, r0 = ri >> 3;
            float vv[4] = {v.x, v.y, v.z, v.w};
            #pragma unroll
            for (int c = 0; c < 4; c++) {
                const int d  = dq * 4 + c;
                const int kt = d >> 3, dk = d & 7;
                const int tg = dk & 3, r1 = dk >> 2;
                XS[((mt*8 + kt)*32 + gg*4 + tg)*4 + r0 + 2*r1] = f2tf(vv[c]);
            }
        }

        __syncthreads();   // bar2: XS ready

        // gating layer1 (warps 0-3), then named-bar with warp 4 only
        if (w < 4) {
            #pragma unroll
            for (int mt = 0; mt < MT; mt++) {
                float ga[4] = {gba, gbb, gba, gbb};
                #pragma unroll
                for (int kt = 0; kt < 4; kt++) {
                    uint4 av = XSv[(mt*8 + 4 + kt)*32 + lane];
                    mma_tf32(ga, av.x, av.y, av.z, av.w, gf0[kt], gf1[kt]);
                }
                const int r = mt*16 + g;
                GHu[r*33     + w*8 + 2*tig    ] = f2tf(fmaxf(ga[0], 0.f));
                GHu[r*33     + w*8 + 2*tig + 1] = f2tf(fmaxf(ga[1], 0.f));
                GHu[(r+8)*33 + w*8 + 2*tig    ] = f2tf(fmaxf(ga[2], 0.f));
                GHu[(r+8)*33 + w*8 + 2*tig + 1] = f2tf(fmaxf(ga[3], 0.f));
            }
            asm volatile("bar.sync 1, 160;" ::: "memory");
        } else if (w == 4) {
            asm volatile("bar.sync 1, 160;" ::: "memory");
            #pragma unroll
            for (int mt = 0; mt < MT; mt++) {
                float la[4] = {gba, gbb, gba, gbb};
                const int r = mt*16 + g;
                #pragma unroll
                for (int kt = 0; kt < 4; kt++) {
                    unsigned a0 = GHu[r*33     + kt*8 + tig    ];
                    unsigned a1 = GHu[(r+8)*33 + kt*8 + tig    ];
                    unsigned a2 = GHu[r*33     + kt*8 + tig + 4];
                    unsigned a3 = GHu[(r+8)*33 + kt*8 + tig + 4];
                    mma_tf32(la, a0, a1, a2, a3, gf0[kt], gf1[kt]);
                }
                float m0 = fmaxf(la[0], la[1]);
                m0 = fmaxf(m0, __shfl_xor_sync(0xffffffffu, m0, 1));
                m0 = fmaxf(m0, __shfl_xor_sync(0xffffffffu, m0, 2));
                float e0 = __expf(la[0] - m0), e1 = __expf(la[1] - m0);
                float s0 = e0 + e1;
                s0 += __shfl_xor_sync(0xffffffffu, s0, 1);
                s0 += __shfl_xor_sync(0xffffffffu, s0, 2);
                float inv0 = 1.f / s0;
                Psm[r*9 + 2*tig    ] = e0 * inv0;
                Psm[r*9 + 2*tig + 1] = e1 * inv0;
                float m1 = fmaxf(la[2], la[3]);
                m1 = fmaxf(m1, __shfl_xor_sync(0xffffffffu, m1, 1));
                m1 = fmaxf(m1, __shfl_xor_sync(0xffffffffu, m1, 2));
                float e2 = __expf(la[2] - m1), e3 = __expf(la[3] - m1);
                float s1 = e2 + e3;
                s1 += __shfl_xor_sync(0xffffffffu, s1, 1);
                s1 += __shfl_xor_sync(0xffffffffu, s1, 2);
                float inv1 = 1.f / s1;
                Psm[(r+8)*9 + 2*tig    ] = e2 * inv1;
                Psm[(r+8)*9 + 2*tig + 1] = e3 * inv1;
            }
        }

        // expert GEMM + epilogue (all 16 warps; warp handles expert e, n-half nh)
        #pragma unroll 1
        for (int mt = 0; mt < MT; mt++) {
            float acc[4][4];
            #pragma unroll
            for (int nt = 0; nt < 4; nt++) {
                const float2 bv = *(const float2*)(sb1 + e*NH + (nh*4 + nt)*8 + 2*tig);
                acc[nt][0] = bv.x; acc[nt][1] = bv.y;
                acc[nt][2] = bv.x; acc[nt][3] = bv.y;
            }
            #pragma unroll
            for (int kt = 0; kt < 8; kt++) {
                uint4 av = XSv[(mt*8 + kt)*32 + lane];
                #pragma unroll
                for (int nt = 0; nt < 4; nt++)
                    mma_tf32(acc[nt], av.x, av.y, av.z, av.w,
                             bf[nt][kt][0], bf[nt][kt][1]);
            }
            float pg = 0.f, ph = 0.f;
            #pragma unroll
            for (int nt = 0; nt < 4; nt++) {
                const float2 wv = *(const float2*)(sw2 + e*NH + (nh*4 + nt)*8 + 2*tig);
                pg = fmaf(fmaxf(acc[nt][0], 0.f), wv.x, pg);
                pg = fmaf(fmaxf(acc[nt][1], 0.f), wv.y, pg);
                ph = fmaf(fmaxf(acc[nt][2], 0.f), wv.x, ph);
                ph = fmaf(fmaxf(acc[nt][3], 0.f), wv.y, ph);
            }
            pg += __shfl_xor_sync(0xffffffffu, pg, 1);
            pg += __shfl_xor_sync(0xffffffffu, pg, 2);
            ph += __shfl_xor_sync(0xffffffffu, ph, 1);
            ph += __shfl_xor_sync(0xffffffffu, ph, 2);
            if (tig == 0) {
                const int r = mt*16 + g;
                const float bias = nh ? 0.f : sb2[e];
                EO[r*18     + 2*e + nh] = pg + bias;
                EO[(r+8)*18 + 2*e + nh] = ph + bias;
            }
        }
    }

    __syncthreads();
    if (tid < TOK_TILE) {
        float a = 0.f;
        #pragma unroll
        for (int ee = 0; ee < NE; ee++)
            a = fmaf(Psm[tid*9 + ee], EO[tid*18 + 2*ee] + EO[tid*18 + 2*ee + 1], a);
        out[ctaBase + (NTILES-1)*TOK_TILE + tid] = a;
    }
}

extern "C" void kernel_launch(void* const* d_in, const int* in_sizes, int n_in,
                              void* d_out, int out_size)
{
    const float* A   = (const float*)d_in[0];
    const float* S   = (const float*)d_in[1];
    const float* gw1 = (const float*)d_in[2];
    const float* gb1 = (const float*)d_in[3];
    const float* gw2 = (const float*)d_in[4];
    const float* gb2 = (const float*)d_in[5];
    const float* ew1 = (const float*)d_in[6];
    const float* eb1 = (const float*)d_in[7];
    const float* ew2 = (const float*)d_in[8];
    const float* eb2 = (const float*)d_in[9];
    float* out = (float*)d_out;

    const int b = in_sizes[0] / 32;          // 524288 tokens
    moe_mma_kernel<<<b / TOK_CTA, TPB>>>(A, S, gw1, gb1, gw2, gb2,
                                         ew1, eb1, ew2, eb2, out);
}

// round 4
// speedup vs baseline: 1.1540x; 1.1540x over previous
#include <cuda_runtime.h>

#define TPB       512
#define TOK_CTA   256
#define TOK_TILE  64
#define NTILES    (TOK_CTA / TOK_TILE)   // 4
#define MT        (TOK_TILE / 16)        // 4 m-tiles per tile
#define NE        8
#define NH        64
#define DIM       64
#define GHD       32

__device__ __forceinline__ unsigned f2tf(float f) {
    unsigned u;
    asm("cvt.rna.tf32.f32 %0, %1;" : "=r"(u) : "f"(f));
    return u;
}
__device__ __forceinline__ void mma_tf32(float* c,
                                         unsigned a0, unsigned a1, unsigned a2, unsigned a3,
                                         unsigned b0, unsigned b1) {
    asm volatile(
        "mma.sync.aligned.m16n8k8.row.col.f32.tf32.tf32.f32 "
        "{%0,%1,%2,%3}, {%4,%5,%6,%7}, {%8,%9}, {%0,%1,%2,%3};\n"
        : "+f"(c[0]), "+f"(c[1]), "+f"(c[2]), "+f"(c[3])
        : "r"(a0), "r"(a1), "r"(a2), "r"(a3), "r"(b0), "r"(b1));
}

__global__ void __launch_bounds__(TPB, 1)
moe_mma_kernel(const float* __restrict__ A,  const float* __restrict__ S,
               const float* __restrict__ gw1, const float* __restrict__ gb1,
               const float* __restrict__ gw2, const float* __restrict__ gb2,
               const float* __restrict__ ew1, const float* __restrict__ eb1,
               const float* __restrict__ ew2, const float* __restrict__ eb2,
               float* __restrict__ out)
{
    __shared__ uint4    XSv[MT * 8 * 32];     // A-frags, 16KB
    __shared__ unsigned GHu[TOK_TILE * 33];   // gating hidden (tf32 bits)
    __shared__ float    EO[TOK_TILE * 18];    // [token][expert*2+half]
    __shared__ float    Psm[TOK_TILE * 9];    // gating probs
    __shared__ float    sw2[NE * NH];
    __shared__ float    sb1[NE * NH];
    __shared__ float    sb2[NE];

    const int tid  = threadIdx.x;
    const int w    = tid >> 5;                // 0..15
    const int lane = tid & 31;
    const int g    = lane >> 2;
    const int tig  = lane & 3;
    const int e    = w >> 1;                  // expert id
    const int nh   = w & 1;                   // n-half (nt base = nh*4)

    for (int i = tid; i < NE * NH; i += TPB) { sw2[i] = ew2[i]; sb1[i] = eb1[i]; }
    if (tid < NE) sb2[tid] = eb2[tid];

    // expert B-fragments: 4 n-tiles x 8 k-tiles = 64 regs (fits: 1 CTA/SM, ~128 reg budget)
    unsigned bf[4][8][2];
    {
        const float* we = ew1 + e * (DIM * NH);
        #pragma unroll
        for (int nt = 0; nt < 4; nt++)
            #pragma unroll
            for (int kt = 0; kt < 8; kt++) {
                const int ncol = (nh*4 + nt)*8 + g;
                bf[nt][kt][0] = f2tf(we[(kt*8 + tig    ) * NH + ncol]);
                bf[nt][kt][1] = f2tf(we[(kt*8 + tig + 4) * NH + ncol]);
            }
    }

    // gating fragments (warps 0-3: layer1 n-tile w; warp 4: layer2) — shared regs
    unsigned gf0[4], gf1[4]; float gba = 0.f, gbb = 0.f;
    if (w < 4) {
        #pragma unroll
        for (int kt = 0; kt < 4; kt++) {
            gf0[kt] = f2tf(gw1[(kt*8 + tig    ) * GHD + w*8 + g]);
            gf1[kt] = f2tf(gw1[(kt*8 + tig + 4) * GHD + w*8 + g]);
        }
        gba = gb1[w*8 + 2*tig];
        gbb = gb1[w*8 + 2*tig + 1];
    } else if (w == 4) {
        #pragma unroll
        for (int kt = 0; kt < 4; kt++) {
            gf0[kt] = f2tf(gw2[(kt*8 + tig    ) * NE + g]);
            gf1[kt] = f2tf(gw2[(kt*8 + tig + 4) * NE + g]);
        }
        gba = gb2[2*tig];
        gbb = gb2[2*tig + 1];
    }

    const int ctaBase = blockIdx.x * TOK_CTA;
    unsigned* XS = (unsigned*)XSv;

    #pragma unroll 1
    for (int it = 0; it < NTILES; it++) {
        const int tb = ctaBase + it * TOK_TILE;

        __syncthreads();   // bar1: prev EO/Psm consumed below; XS free

        if (it > 0 && tid < TOK_TILE) {
            float a = 0.f;
            #pragma unroll
            for (int ee = 0; ee < NE; ee++)
                a = fmaf(Psm[tid*9 + ee], EO[tid*18 + 2*ee] + EO[tid*18 + 2*ee + 1], a);
            out[tb - TOK_TILE + tid] = a;
        }

        // stage 64 tokens into A-fragment-ordered smem
        #pragma unroll
        for (int j = tid; j < TOK_TILE * 16; j += TPB) {
            const int t  = j >> 4;
            const int dq = j & 15;
            float4 v;
            if (dq < 8) v = ((const float4*)A)[(size_t)(tb + t) * 8 + dq];
            else        v = ((const float4*)S)[(size_t)(tb + t) * 8 + (dq - 8)];
            const int mt = t >> 4, ri = t & 15;
            const int gg = ri & 7, r0 = ri >> 3;
            float vv[4] = {v.x, v.y, v.z, v.w};
            #pragma unroll
            for (int c = 0; c < 4; c++) {
                const int d  = dq * 4 + c;
                const int kt = d >> 3, dk = d & 7;
                const int tg = dk & 3, r1 = dk >> 2;
                XS[((mt*8 + kt)*32 + gg*4 + tg)*4 + r0 + 2*r1] = f2tf(vv[c]);
            }
        }

        __syncthreads();   // bar2: XS ready

        // gating layer1 (warps 0-3), then named-bar with warp 4 only
        if (w < 4) {
            #pragma unroll
            for (int mt = 0; mt < MT; mt++) {
                float ga[4] = {gba, gbb, gba, gbb};
                #pragma unroll
                for (int kt = 0; kt < 4; kt++) {
                    uint4 av = XSv[(mt*8 + 4 + kt)*32 + lane];
                    mma_tf32(ga, av.x, av.y, av.z, av.w, gf0[kt], gf1[kt]);
                }
                const int r = mt*16 + g;
                GHu[r*33     + w*8 + 2*tig    ] = f2tf(fmaxf(ga[0], 0.f));
                GHu[r*33     + w*8 + 2*tig + 1] = f2tf(fmaxf(ga[1], 0.f));
                GHu[(r+8)*33 + w*8 + 2*tig    ] = f2tf(fmaxf(ga[2], 0.f));
                GHu[(r+8)*33 + w*8 + 2*tig + 1] = f2tf(fmaxf(ga[3], 0.f));
            }
            asm volatile("bar.sync 1, 160;" ::: "memory");
        } else if (w == 4) {
            asm volatile("bar.sync 1, 160;" ::: "memory");
            #pragma unroll
            for (int mt = 0; mt < MT; mt++) {
                float la[4] = {gba, gbb, gba, gbb};
                const int r = mt*16 + g;
                #pragma unroll
                for (int kt = 0; kt < 4; kt++) {
                    unsigned a0 = GHu[r*33     + kt*8 + tig    ];
                    unsigned a1 = GHu[(r+8)*33 + kt*8 + tig    ];
                    unsigned a2 = GHu[r*33     + kt*8 + tig + 4];
                    unsigned a3 = GHu[(r+8)*33 + kt*8 + tig + 4];
                    mma_tf32(la, a0, a1, a2, a3, gf0[kt], gf1[kt]);
                }
                float m0 = fmaxf(la[0], la[1]);
                m0 = fmaxf(m0, __shfl_xor_sync(0xffffffffu, m0, 1));
                m0 = fmaxf(m0, __shfl_xor_sync(0xffffffffu, m0, 2));
                float e0 = __expf(la[0] - m0), e1 = __expf(la[1] - m0);
                float s0 = e0 + e1;
                s0 += __shfl_xor_sync(0xffffffffu, s0, 1);
                s0 += __shfl_xor_sync(0xffffffffu, s0, 2);
                float inv0 = 1.f / s0;
                Psm[r*9 + 2*tig    ] = e0 * inv0;
                Psm[r*9 + 2*tig + 1] = e1 * inv0;
                float m1 = fmaxf(la[2], la[3]);
                m1 = fmaxf(m1, __shfl_xor_sync(0xffffffffu, m1, 1));
                m1 = fmaxf(m1, __shfl_xor_sync(0xffffffffu, m1, 2));
                float e2 = __expf(la[2] - m1), e3 = __expf(la[3] - m1);
                float s1 = e2 + e3;
                s1 += __shfl_xor_sync(0xffffffffu, s1, 1);
                s1 += __shfl_xor_sync(0xffffffffu, s1, 2);
                float inv1 = 1.f / s1;
                Psm[(r+8)*9 + 2*tig    ] = e2 * inv1;
                Psm[(r+8)*9 + 2*tig + 1] = e3 * inv1;
            }
        }

        // expert GEMM + epilogue (all 16 warps; warp handles expert e, n-half nh)
        #pragma unroll 1
        for (int mt = 0; mt < MT; mt++) {
            float acc[4][4];
            #pragma unroll
            for (int nt = 0; nt < 4; nt++) {
                const float2 bv = *(const float2*)(sb1 + e*NH + (nh*4 + nt)*8 + 2*tig);
                acc[nt][0] = bv.x; acc[nt][1] = bv.y;
                acc[nt][2] = bv.x; acc[nt][3] = bv.y;
            }
            #pragma unroll
            for (int kt = 0; kt < 8; kt++) {
                uint4 av = XSv[(mt*8 + kt)*32 + lane];
                #pragma unroll
                for (int nt = 0; nt < 4; nt++)
                    mma_tf32(acc[nt], av.x, av.y, av.z, av.w,
                             bf[nt][kt][0], bf[nt][kt][1]);
            }
            float pg = 0.f, ph = 0.f;
            #pragma unroll
            for (int nt = 0; nt < 4; nt++) {
                const float2 wv = *(const float2*)(sw2 + e*NH + (nh*4 + nt)*8 + 2*tig);
                pg = fmaf(fmaxf(acc[nt][0], 0.f), wv.x, pg);
                pg = fmaf(fmaxf(acc[nt][1], 0.f), wv.y, pg);
                ph = fmaf(fmaxf(acc[nt][2], 0.f), wv.x, ph);
                ph = fmaf(fmaxf(acc[nt][3], 0.f), wv.y, ph);
            }
            pg += __shfl_xor_sync(0xffffffffu, pg, 1);
            pg += __shfl_xor_sync(0xffffffffu, pg, 2);
            ph += __shfl_xor_sync(0xffffffffu, ph, 1);
            ph += __shfl_xor_sync(0xffffffffu, ph, 2);
            if (tig == 0) {
                const int r = mt*16 + g;
                const float bias = nh ? 0.f : sb2[e];
                EO[r*18     + 2*e + nh] = pg + bias;
                EO[(r+8)*18 + 2*e + nh] = ph + bias;
            }
        }
    }

    __syncthreads();
    if (tid < TOK_TILE) {
        float a = 0.f;
        #pragma unroll
        for (int ee = 0; ee < NE; ee++)
            a = fmaf(Psm[tid*9 + ee], EO[tid*18 + 2*ee] + EO[tid*18 + 2*ee + 1], a);
        out[ctaBase + (NTILES-1)*TOK_TILE + tid] = a;
    }
}

extern "C" void kernel_launch(void* const* d_in, const int* in_sizes, int n_in,
                              void* d_out, int out_size)
{
    const float* A   = (const float*)d_in[0];
    const float* S   = (const float*)d_in[1];
    const float* gw1 = (const float*)d_in[2];
    const float* gb1 = (const float*)d_in[3];
    const float* gw2 = (const float*)d_in[4];
    const float* gb2 = (const float*)d_in[5];
    const float* ew1 = (const float*)d_in[6];
    const float* eb1 = (const float*)d_in[7];
    const float* ew2 = (const float*)d_in[8];
    const float* eb2 = (const float*)d_in[9];
    float* out = (float*)d_out;

    const int b = in_sizes[0] / 32;          // 524288 tokens
    moe_mma_kernel<<<b / TOK_CTA, TPB>>>(A, S, gw1, gb1, gw2, gb2,
                                         ew1, eb1, ew2, eb2, out);
}

// round 5
// speedup vs baseline: 1.2063x; 1.0453x over previous
#include <cuda_runtime.h>

#define TPB       512
#define TOK_CTA   256
#define TOK_TILE  64
#define NTILES    (TOK_CTA / TOK_TILE)   // 4
#define MT        (TOK_TILE / 16)        // 4 m-tiles per tile
#define NE        8
#define NH        64
#define DIM       64
#define GHD       32

// dynamic smem layout (bytes)
#define OFF_XS   0                        // 2 * 1024 uint4 = 32768
#define OFF_GH   32768                    // 64*33 u32      = 8448
#define OFF_EO   41216                    // 2 * 64*18 f    = 9216
#define OFF_P    50432                    // 2 * 64*9  f    = 4608
#define OFF_W2   55040                    // 512 f          = 2048
#define OFF_B1   57088                    // 512 f          = 2048
#define OFF_B2   59136                    // 8 f            = 32
#define SMEM_BYTES 59168

__device__ __forceinline__ unsigned f2tf(float f) {
    unsigned u;
    asm("cvt.rna.tf32.f32 %0, %1;" : "=r"(u) : "f"(f));
    return u;
}
__device__ __forceinline__ void mma_tf32(float* c,
                                         unsigned a0, unsigned a1, unsigned a2, unsigned a3,
                                         unsigned b0, unsigned b1) {
    asm volatile(
        "mma.sync.aligned.m16n8k8.row.col.f32.tf32.tf32.f32 "
        "{%0,%1,%2,%3}, {%4,%5,%6,%7}, {%8,%9}, {%0,%1,%2,%3};\n"
        : "+f"(c[0]), "+f"(c[1]), "+f"(c[2]), "+f"(c[3])
        : "r"(a0), "r"(a1), "r"(a2), "r"(a3), "r"(b0), "r"(b1));
}

// gather one float4 of token data (j in [0,1024): token t=j>>4, quad dq=j&15)
__device__ __forceinline__ float4 ld_tok(const float* __restrict__ A,
                                         const float* __restrict__ S,
                                         int tb, int j) {
    const int t = j >> 4, dq = j & 15;
    if (dq < 8) return ((const float4*)A)[(size_t)(tb + t) * 8 + dq];
    return ((const float4*)S)[(size_t)(tb + t) * 8 + (dq - 8)];
}
// scatter it into A-fragment order (tf32 bits)
__device__ __forceinline__ void st_frag(unsigned* XS, int j, float4 v) {
    const int t = j >> 4, dq = j & 15;
    const int mt = t >> 4, ri = t & 15;
    const int gg = ri & 7, r0 = ri >> 3;
    float vv[4] = {v.x, v.y, v.z, v.w};
    #pragma unroll
    for (int c = 0; c < 4; c++) {
        const int d  = dq * 4 + c;
        const int kt = d >> 3, dk = d & 7;
        const int tg = dk & 3, r1 = dk >> 2;
        XS[((mt*8 + kt)*32 + gg*4 + tg)*4 + r0 + 2*r1] = f2tf(vv[c]);
    }
}

__global__ void __launch_bounds__(TPB, 1)
moe_mma_kernel(const float* __restrict__ A,  const float* __restrict__ S,
               const float* __restrict__ gw1, const float* __restrict__ gb1,
               const float* __restrict__ gw2, const float* __restrict__ gb2,
               const float* __restrict__ ew1, const float* __restrict__ eb1,
               const float* __restrict__ ew2, const float* __restrict__ eb2,
               float* __restrict__ out)
{
    extern __shared__ char smraw[];
    uint4*    XSv = (uint4*)(smraw + OFF_XS);
    unsigned* GHu = (unsigned*)(smraw + OFF_GH);
    float*    EO  = (float*)(smraw + OFF_EO);
    float*    Psm = (float*)(smraw + OFF_P);
    float*    sw2 = (float*)(smraw + OFF_W2);
    float*    sb1 = (float*)(smraw + OFF_B1);
    float*    sb2 = (float*)(smraw + OFF_B2);

    const int tid  = threadIdx.x;
    const int w    = tid >> 5;
    const int lane = tid & 31;
    const int g    = lane >> 2;
    const int tig  = lane & 3;
    const int e    = w >> 1;
    const int nh   = w & 1;

    for (int i = tid; i < NE * NH; i += TPB) { sw2[i] = ew2[i]; sb1[i] = eb1[i]; }
    if (tid < NE) sb2[tid] = eb2[tid];

    // expert B-fragments: 64 regs
    unsigned bf[4][8][2];
    {
        const float* we = ew1 + e * (DIM * NH);
        #pragma unroll
        for (int nt = 0; nt < 4; nt++)
            #pragma unroll
            for (int kt = 0; kt < 8; kt++) {
                const int ncol = (nh*4 + nt)*8 + g;
                bf[nt][kt][0] = f2tf(we[(kt*8 + tig    ) * NH + ncol]);
                bf[nt][kt][1] = f2tf(we[(kt*8 + tig + 4) * NH + ncol]);
            }
    }

    // gating fragments (warps 0-3: layer1; warp 4: layer2)
    unsigned gf0[4], gf1[4]; float gba = 0.f, gbb = 0.f;
    if (w < 4) {
        #pragma unroll
        for (int kt = 0; kt < 4; kt++) {
            gf0[kt] = f2tf(gw1[(kt*8 + tig    ) * GHD + w*8 + g]);
            gf1[kt] = f2tf(gw1[(kt*8 + tig + 4) * GHD + w*8 + g]);
        }
        gba = gb1[w*8 + 2*tig];
        gbb = gb1[w*8 + 2*tig + 1];
    } else if (w == 4) {
        #pragma unroll
        for (int kt = 0; kt < 4; kt++) {
            gf0[kt] = f2tf(gw2[(kt*8 + tig    ) * NE + g]);
            gf1[kt] = f2tf(gw2[(kt*8 + tig + 4) * NE + g]);
        }
        gba = gb2[2*tig];
        gbb = gb2[2*tig + 1];
    }

    const int ctaBase = blockIdx.x * TOK_CTA;

    // pre-stage tile 0 into buffer 0
    {
        unsigned* XS0 = (unsigned*)XSv;
        #pragma unroll
        for (int k = 0; k < 2; k++) {
            const int j = tid + k * TPB;
            st_frag(XS0, j, ld_tok(A, S, ctaBase, j));
        }
    }
    __syncthreads();

    #pragma unroll 1
    for (int it = 0; it < NTILES; it++) {
        const int p  = it & 1;
        const int tb = ctaBase + it * TOK_TILE;
        uint4*    Xc  = XSv + p * 1024;
        float*    EOp = EO  + p * (TOK_TILE * 18);
        float*    Pp  = Psm + p * (TOK_TILE * 9);

        // prefetch next tile's global data into registers (batched LDGs)
        float4 pf0, pf1;
        if (it + 1 < NTILES) {
            pf0 = ld_tok(A, S, tb + TOK_TILE, tid);
            pf1 = ld_tok(A, S, tb + TOK_TILE, tid + TPB);
        }

        // ---- gating (warps 0-4) ----
        if (w < 4) {
            #pragma unroll
            for (int mt = 0; mt < MT; mt++) {
                float ga[4] = {gba, gbb, gba, gbb};
                #pragma unroll
                for (int kt = 0; kt < 4; kt++) {
                    uint4 av = Xc[(mt*8 + 4 + kt)*32 + lane];
                    mma_tf32(ga, av.x, av.y, av.z, av.w, gf0[kt], gf1[kt]);
                }
                const int r = mt*16 + g;
                GHu[r*33     + w*8 + 2*tig    ] = f2tf(fmaxf(ga[0], 0.f));
                GHu[r*33     + w*8 + 2*tig + 1] = f2tf(fmaxf(ga[1], 0.f));
                GHu[(r+8)*33 + w*8 + 2*tig    ] = f2tf(fmaxf(ga[2], 0.f));
                GHu[(r+8)*33 + w*8 + 2*tig + 1] = f2tf(fmaxf(ga[3], 0.f));
            }
            asm volatile("bar.sync 1, 160;" ::: "memory");
        } else if (w == 4) {
            asm volatile("bar.sync 1, 160;" ::: "memory");
            #pragma unroll
            for (int mt = 0; mt < MT; mt++) {
                float la[4] = {gba, gbb, gba, gbb};
                const int r = mt*16 + g;
                #pragma unroll
                for (int kt = 0; kt < 4; kt++) {
                    unsigned a0 = GHu[r*33     + kt*8 + tig    ];
                    unsigned a1 = GHu[(r+8)*33 + kt*8 + tig    ];
                    unsigned a2 = GHu[r*33     + kt*8 + tig + 4];
                    unsigned a3 = GHu[(r+8)*33 + kt*8 + tig + 4];
                    mma_tf32(la, a0, a1, a2, a3, gf0[kt], gf1[kt]);
                }
                float m0 = fmaxf(la[0], la[1]);
                m0 = fmaxf(m0, __shfl_xor_sync(0xffffffffu, m0, 1));
                m0 = fmaxf(m0, __shfl_xor_sync(0xffffffffu, m0, 2));
                float e0 = __expf(la[0] - m0), e1 = __expf(la[1] - m0);
                float s0 = e0 + e1;
                s0 += __shfl_xor_sync(0xffffffffu, s0, 1);
                s0 += __shfl_xor_sync(0xffffffffu, s0, 2);
                float inv0 = 1.f / s0;
                Pp[r*9 + 2*tig    ] = e0 * inv0;
                Pp[r*9 + 2*tig + 1] = e1 * inv0;
                float m1 = fmaxf(la[2], la[3]);
                m1 = fmaxf(m1, __shfl_xor_sync(0xffffffffu, m1, 1));
                m1 = fmaxf(m1, __shfl_xor_sync(0xffffffffu, m1, 2));
                float e2 = __expf(la[2] - m1), e3 = __expf(la[3] - m1);
                float s1 = e2 + e3;
                s1 += __shfl_xor_sync(0xffffffffu, s1, 1);
                s1 += __shfl_xor_sync(0xffffffffu, s1, 2);
                float inv1 = 1.f / s1;
                Pp[(r+8)*9 + 2*tig    ] = e2 * inv1;
                Pp[(r+8)*9 + 2*tig + 1] = e3 * inv1;
            }
        }

        // ---- expert GEMM + epilogue ----
        #pragma unroll 1
        for (int mt = 0; mt < MT; mt++) {
            float acc[4][4];
            #pragma unroll
            for (int nt = 0; nt < 4; nt++) {
                const float2 bv = *(const float2*)(sb1 + e*NH + (nh*4 + nt)*8 + 2*tig);
                acc[nt][0] = bv.x; acc[nt][1] = bv.y;
                acc[nt][2] = bv.x; acc[nt][3] = bv.y;
            }
            #pragma unroll
            for (int kt = 0; kt < 8; kt++) {
                uint4 av = Xc[(mt*8 + kt)*32 + lane];
                #pragma unroll
                for (int nt = 0; nt < 4; nt++)
                    mma_tf32(acc[nt], av.x, av.y, av.z, av.w,
                             bf[nt][kt][0], bf[nt][kt][1]);
            }
            float pg = 0.f, ph = 0.f;
            #pragma unroll
            for (int nt = 0; nt < 4; nt++) {
                const float2 wv = *(const float2*)(sw2 + e*NH + (nh*4 + nt)*8 + 2*tig);
                pg = fmaf(fmaxf(acc[nt][0], 0.f), wv.x, pg);
                pg = fmaf(fmaxf(acc[nt][1], 0.f), wv.y, pg);
                ph = fmaf(fmaxf(acc[nt][2], 0.f), wv.x, ph);
                ph = fmaf(fmaxf(acc[nt][3], 0.f), wv.y, ph);
            }
            pg += __shfl_xor_sync(0xffffffffu, pg, 1);
            pg += __shfl_xor_sync(0xffffffffu, pg, 2);
            ph += __shfl_xor_sync(0xffffffffu, ph, 1);
            ph += __shfl_xor_sync(0xffffffffu, ph, 2);
            if (tig == 0) {
                const int r = mt*16 + g;
                const float bias = nh ? 0.f : sb2[e];
                EOp[r*18     + 2*e + nh] = pg + bias;
                EOp[(r+8)*18 + 2*e + nh] = ph + bias;
            }
        }

        // ---- stage prefetched data into the other buffer ----
        if (it + 1 < NTILES) {
            unsigned* Xn = (unsigned*)(XSv + (p ^ 1) * 1024);
            st_frag(Xn, tid,       pf0);
            st_frag(Xn, tid + TPB, pf1);
        }

        __syncthreads();   // staging done + EO/Psm(p) complete

        // ---- combine this tile's output ----
        if (tid < TOK_TILE) {
            float a = 0.f;
            #pragma unroll
            for (int ee = 0; ee < NE; ee++)
                a = fmaf(Pp[tid*9 + ee], EOp[tid*18 + 2*ee] + EOp[tid*18 + 2*ee + 1], a);
            out[tb + tid] = a;
        }
    }
}

extern "C" void kernel_launch(void* const* d_in, const int* in_sizes, int n_in,
                              void* d_out, int out_size)
{
    const float* A   = (const float*)d_in[0];
    const float* S   = (const float*)d_in[1];
    const float* gw1 = (const float*)d_in[2];
    const float* gb1 = (const float*)d_in[3];
    const float* gw2 = (const float*)d_in[4];
    const float* gb2 = (const float*)d_in[5];
    const float* ew1 = (const float*)d_in[6];
    const float* eb1 = (const float*)d_in[7];
    const float* ew2 = (const float*)d_in[8];
    const float* eb2 = (const float*)d_in[9];
    float* out = (float*)d_out;

    cudaFuncSetAttribute(moe_mma_kernel,
                         cudaFuncAttributeMaxDynamicSharedMemorySize, SMEM_BYTES);

    const int b = in_sizes[0] / 32;          // 524288 tokens
    moe_mma_kernel<<<b / TOK_CTA, TPB, SMEM_BYTES>>>(A, S, gw1, gb1, gw2, gb2,
                                                     ew1, eb1, ew2, eb2, out);
}

// round 10
// speedup vs baseline: 2.4772x; 2.0536x over previous
#include <cuda_runtime.h>
#include <cstdint>

#define TPB       256
#define TOK_CTA   512
#define TILE      64
#define NTILES    (TOK_CTA / TILE)   // 8
#define NMT       4                  // m-tiles (16 rows each)
#define NKT       4                  // k-tiles (k16 each) over DIM=64
#define NE        8
#define NH        64
#define GHD       32

// pack two floats -> f16x2 (lo=a, hi=b)
__device__ __forceinline__ unsigned ph2(float a, float b) {
    unsigned r;
    asm("cvt.rn.f16x2.f32 %0, %2, %1;" : "=r"(r) : "f"(a), "f"(b));
    return r;
}
__device__ __forceinline__ void mma_f16(float* c,
                                        unsigned a0, unsigned a1, unsigned a2, unsigned a3,
                                        unsigned b0, unsigned b1) {
    asm volatile(
        "mma.sync.aligned.m16n8k16.row.col.f32.f16.f16.f32 "
        "{%0,%1,%2,%3}, {%4,%5,%6,%7}, {%8,%9}, {%0,%1,%2,%3};\n"
        : "+f"(c[0]), "+f"(c[1]), "+f"(c[2]), "+f"(c[3])
        : "r"(a0), "r"(a1), "r"(a2), "r"(a3), "r"(b0), "r"(b1));
}

__global__ void __launch_bounds__(TPB, 2)
moe_f16_kernel(const float* __restrict__ A,  const float* __restrict__ S,
               const float* __restrict__ gw1, const float* __restrict__ gb1,
               const float* __restrict__ gw2, const float* __restrict__ gb2,
               const float* __restrict__ ew1, const float* __restrict__ eb1,
               const float* __restrict__ ew2, const float* __restrict__ eb2,
               float* __restrict__ out)
{
    // A-fragments of X tile: group (mt*4+kt) stride 33 uint4 (bank skew)
    __shared__ uint4 XSv[16 * 33];          // 8448 B
    __shared__ uint4 GH4[8 * 33];           // gating hidden as A-frags, 4224 B
    __shared__ float EO[2][TILE * 9];       // expert outputs
    __shared__ float Pf[2][TILE * 9];       // gating probs
    __shared__ uint2 sgf1[8 * 32];          // gating l1 B-frags [(w*2+kt)*32+lane]
    __shared__ uint2 sgf2[2 * 32];          // gating l2 B-frags
    __shared__ float sw2[NE * NH];
    __shared__ float sb1[NE * NH];

    const int tid  = threadIdx.x;
    const int w    = tid >> 5;              // warp id == expert id (0..7)
    const int lane = tid & 31;
    const int g    = lane >> 2;
    const int tig  = lane & 3;

    // ---- small tensors ----
    for (int i = tid; i < NE * NH; i += TPB) { sw2[i] = ew2[i]; sb1[i] = eb1[i]; }
    const float sb2e = eb2[w];

    // ---- expert B-fragments (fp16): 8 nt x 4 kt x 2 = 64 regs ----
    unsigned bf[8][4][2];
    {
        const float* we = ew1 + w * (64 * NH);
        #pragma unroll
        for (int nt = 0; nt < 8; nt++)
            #pragma unroll
            for (int kt = 0; kt < 4; kt++) {
                const int k0 = kt*16 + 2*tig;
                const int n  = nt*8 + g;
                bf[nt][kt][0] = ph2(we[k0*NH + n],     we[(k0+1)*NH + n]);
                bf[nt][kt][1] = ph2(we[(k0+8)*NH + n], we[(k0+9)*NH + n]);
            }
    }

    // ---- gating B-frags into smem (once); biases in 2 regs ----
    float gba = 0.f, gbb = 0.f;
    if (w < 4) {
        #pragma unroll
        for (int kt = 0; kt < 2; kt++) {
            const int k0 = kt*16 + 2*tig;
            const int n  = w*8 + g;
            sgf1[(w*2+kt)*32 + lane] =
                make_uint2(ph2(gw1[k0*GHD + n],     gw1[(k0+1)*GHD + n]),
                           ph2(gw1[(k0+8)*GHD + n], gw1[(k0+9)*GHD + n]));
        }
        gba = gb1[w*8 + 2*tig];
        gbb = gb1[w*8 + 2*tig + 1];
    } else if (w == 4) {
        #pragma unroll
        for (int kt = 0; kt < 2; kt++) {
            const int k0 = kt*16 + 2*tig;
            sgf2[kt*32 + lane] =
                make_uint2(ph2(gw2[k0*NE + g],     gw2[(k0+1)*NE + g]),
                           ph2(gw2[(k0+8)*NE + g], gw2[(k0+9)*NE + g]));
        }
        gba = gb2[2*tig];
        gbb = gb2[2*tig + 1];
    }

    const int ctaBase = blockIdx.x * TOK_CTA;
    unsigned* XSw = (unsigned*)XSv;
    unsigned* GHw = (unsigned*)GH4;

    #pragma unroll 1
    for (int it = 0; it < NTILES; it++) {
        const int p  = it & 1;
        const int tb = ctaBase + it * TILE;

        // ---- stage 64 tokens as fp16 A-fragments ----
        #pragma unroll
        for (int k = 0; k < 4; k++) {
            const int j  = tid + k * TPB;        // 0..1023
            const int t  = j >> 4, dq = j & 15;
            float4 v;
            if (dq < 8) v = ((const float4*)A)[(size_t)(tb + t) * 8 + dq];
            else        v = ((const float4*)S)[(size_t)(tb + t) * 8 + (dq - 8)];
            const int mt  = t >> 4, r = t & 15;
            const int kt  = dq >> 2, dk0 = (dq & 3) * 4;
            const int reg = (r >= 8 ? 1 : 0) + (dk0 >= 8 ? 2 : 0);
            const int l0  = (r & 7) * 4 + ((dk0 & 7) >> 1);
            const int wb  = (((mt*4 + kt)*33 + l0) << 2) + reg;
            XSw[wb]     = ph2(v.x, v.y);
            XSw[wb + 4] = ph2(v.z, v.w);
        }
        __syncthreads();

        // ---- gating (warps 0-4): uses S-half of X frags (kt 2,3) ----
        if (w < 4) {
            #pragma unroll
            for (int mt = 0; mt < NMT; mt++) {
                float ga[4] = {gba, gbb, gba, gbb};
                #pragma unroll
                for (int kt = 0; kt < 2; kt++) {
                    uint4 av = XSv[(mt*4 + 2 + kt)*33 + lane];
                    uint2 bv = sgf1[(w*2 + kt)*32 + lane];
                    mma_f16(ga, av.x, av.y, av.z, av.w, bv.x, bv.y);
                }
                // store relu(hidden) as layer2 A-frags
                const int kt2 = w >> 1;
                const int base = (((mt*2 + kt2)*33 + g*4 + tig) << 2) + 2*(w & 1);
                GHw[base]     = ph2(fmaxf(ga[0], 0.f), fmaxf(ga[1], 0.f));
                GHw[base + 1] = ph2(fmaxf(ga[2], 0.f), fmaxf(ga[3], 0.f));
            }
            asm volatile("bar.sync 1, 160;" ::: "memory");
        } else if (w == 4) {
            asm volatile("bar.sync 1, 160;" ::: "memory");
            #pragma unroll
            for (int mt = 0; mt < NMT; mt++) {
                float la[4] = {gba, gbb, gba, gbb};
                #pragma unroll
                for (int kt = 0; kt < 2; kt++) {
                    uint4 av = GH4[(mt*2 + kt)*33 + lane];
                    uint2 bv = sgf2[kt*32 + lane];
                    mma_f16(la, av.x, av.y, av.z, av.w, bv.x, bv.y);
                }
                const int r = mt*16 + g;
                float m0 = fmaxf(la[0], la[1]);
                m0 = fmaxf(m0, __shfl_xor_sync(0xffffffffu, m0, 1));
                m0 = fmaxf(m0, __shfl_xor_sync(0xffffffffu, m0, 2));
                float e0 = __expf(la[0] - m0), e1 = __expf(la[1] - m0);
                float s0 = e0 + e1;
                s0 += __shfl_xor_sync(0xffffffffu, s0, 1);
                s0 += __shfl_xor_sync(0xffffffffu, s0, 2);
                float inv0 = 1.f / s0;
                Pf[p][r*9 + 2*tig    ] = e0 * inv0;
                Pf[p][r*9 + 2*tig + 1] = e1 * inv0;
                float m1 = fmaxf(la[2], la[3]);
                m1 = fmaxf(m1, __shfl_xor_sync(0xffffffffu, m1, 1));
                m1 = fmaxf(m1, __shfl_xor_sync(0xffffffffu, m1, 2));
                float e2 = __expf(la[2] - m1), e3 = __expf(la[3] - m1);
                float s1 = e2 + e3;
                s1 += __shfl_xor_sync(0xffffffffu, s1, 1);
                s1 += __shfl_xor_sync(0xffffffffu, s1, 2);
                float inv1 = 1.f / s1;
                Pf[p][(r+8)*9 + 2*tig    ] = e2 * inv1;
                Pf[p][(r+8)*9 + 2*tig + 1] = e3 * inv1;
            }
        }

        // ---- expert GEMM + epilogue (all 8 warps; warp = full expert) ----
        #pragma unroll 1
        for (int mt = 0; mt < NMT; mt++) {
            float acc[8][4];
            #pragma unroll
            for (int nt = 0; nt < 8; nt++) {
                const float2 bv = *(const float2*)(sb1 + w*NH + nt*8 + 2*tig);
                acc[nt][0] = bv.x; acc[nt][1] = bv.y;
                acc[nt][2] = bv.x; acc[nt][3] = bv.y;
            }
            #pragma unroll
            for (int kt = 0; kt < NKT; kt++) {
                uint4 av = XSv[(mt*4 + kt)*33 + lane];
                #pragma unroll
                for (int nt = 0; nt < 8; nt++)
                    mma_f16(acc[nt], av.x, av.y, av.z, av.w,
                            bf[nt][kt][0], bf[nt][kt][1]);
            }
            float pg = 0.f, ph = 0.f;
            #pragma unroll
            for (int nt = 0; nt < 8; nt++) {
                const float2 wv = *(const float2*)(sw2 + w*NH + nt*8 + 2*tig);
                pg = fmaf(fmaxf(acc[nt][0], 0.f), wv.x, pg);
                pg = fmaf(fmaxf(acc[nt][1], 0.f), wv.y, pg);
                ph = fmaf(fmaxf(acc[nt][2], 0.f), wv.x, ph);
                ph = fmaf(fmaxf(acc[nt][3], 0.f), wv.y, ph);
            }
            pg += __shfl_xor_sync(0xffffffffu, pg, 1);
            pg += __shfl_xor_sync(0xffffffffu, pg, 2);
            ph += __shfl_xor_sync(0xffffffffu, ph, 1);
            ph += __shfl_xor_sync(0xffffffffu, ph, 2);
            if (tig == 0) {
                const int r = mt*16 + g;
                EO[p][r*9 + w]     = pg + sb2e;
                EO[p][(r+8)*9 + w] = ph + sb2e;
            }
        }

        __syncthreads();

        // ---- combine ----
        if (tid < TILE) {
            float a = 0.f;
            #pragma unroll
            for (int ee = 0; ee < NE; ee++)
                a = fmaf(Pf[p][tid*9 + ee], EO[p][tid*9 + ee], a);
            out[tb + tid] = a;
        }
    }
}

extern "C" void kernel_launch(void* const* d_in, const int* in_sizes, int n_in,
                              void* d_out, int out_size)
{
    const float* A   = (const float*)d_in[0];
    const float* S   = (const float*)d_in[1];
    const float* gw1 = (const float*)d_in[2];
    const float* gb1 = (const float*)d_in[3];
    const float* gw2 = (const float*)d_in[4];
    const float* gb2 = (const float*)d_in[5];
    const float* ew1 = (const float*)d_in[6];
    const float* eb1 = (const float*)d_in[7];
    const float* ew2 = (const float*)d_in[8];
    const float* eb2 = (const float*)d_in[9];
    float* out = (float*)d_out;

    const int b = in_sizes[0] / 32;          // 524288 tokens
    moe_f16_kernel<<<b / TOK_CTA, TPB>>>(A, S, gw1, gb1, gw2, gb2,
                                         ew1, eb1, ew2, eb2, out);
}